// round 16
// baseline (speedup 1.0000x reference)
#include <cuda_runtime.h>
#include <math.h>

// Problem constants (fixed by the reference)
#define NN 6000          // N_USERS + N_ITEMS
#define NNP 6016         // padded row count (multiple of 64) for tiled GEMM
#define EE 100000        // edges
#define NREL 2

#define GRID 256         // persistent blocks (<= 2/SM * 148 SMs guaranteed resident)
#define TPB  256
#define NWARPS (GRID * (TPB / 32))   // 2048 persistent warps

// ---------------------------------------------------------------------------
// Device scratch (static device globals — zero-initialized, no runtime alloc)
// Symbols only referenced inside device code (host-side use would take the
// host shadow address -> silent ATS/C2C traffic, the round-12 bug).
// ---------------------------------------------------------------------------
__device__ int   g_cnt[NN];
__device__ int   g_rowptr[NN + 1];
__device__ int   g_cursor[NN];
__device__ int   g_ssrc[EE];        // CSR (by dst): source node per slot
__device__ int   g_sdst[EE];        // CSR: dst node per slot
__device__ int   g_seid[EE];        // CSR: original edge id per slot
__device__ int   g_stype[EE];       // CSR: edge type per slot

__device__ float g_W0[2 * NN * 32]; // layer-0 relation weights W[r][n][o]
__device__ float g_HRa[NN * 192];   // HR ping
__device__ float g_HRb[NN * 192];   // HR pong
__device__ float g_h[NN * 512];     // GAT h
__device__ float g_xb[NNP * 512];   // GAT output (padded rows stay 0)
__device__ float g_WcAll[6144 + 12288 + 6144]; // fused weights layers 1..3
__device__ float g_asv[NN];
__device__ float g_adv[NN];
__device__ float g_A[NNP * 128];    // x @ w1[0:512]
__device__ float g_B[NNP * 128];    // x @ w1[512:1024]

// grid-barrier state (two-counter scheme; last leaver resets -> replay-safe)
__device__ unsigned g_bar[12];
__device__ unsigned g_done[12];

#define WC1_OFF 0
#define WC2_OFF 6144
#define WC3_OFF 18432

__device__ __forceinline__ float lrelu(float x) { return x > 0.f ? x : 0.2f * x; }

__device__ __forceinline__ float tanh_ap(float x) {
    float r;
    asm("tanh.approx.f32 %0, %1;" : "=f"(r) : "f"(x));
    return r;
}

typedef unsigned long long ull;
__device__ __forceinline__ ull pk2(float lo, float hi) {
    ull r; asm("mov.b64 %0, {%1, %2};" : "=l"(r) : "f"(lo), "f"(hi)); return r;
}
__device__ __forceinline__ void upk2(float& lo, float& hi, ull v) {
    asm("mov.b64 {%0, %1}, %2;" : "=f"(lo), "=f"(hi) : "l"(v));
}
__device__ __forceinline__ void fma2(ull& c, ull a, ull b) {
    asm("fma.rn.f32x2 %0, %1, %2, %0;" : "+l"(c) : "l"(a), "l"(b));
}

// ---------------------------------------------------------------------------
// Software grid barrier. All GRID blocks are co-resident (launch_bounds
// guarantees >=2 blocks/SM), so spinning is deadlock-free. Distinct idx per
// barrier within a launch; counters self-reset for graph replays.
// ---------------------------------------------------------------------------
__device__ __forceinline__ void gbar(int idx) {
    __syncthreads();
    if (threadIdx.x == 0) {
        __threadfence();
        atomicAdd(&g_bar[idx], 1u);
        while (*(volatile unsigned*)&g_bar[idx] < (unsigned)GRID) __nanosleep(64);
        __threadfence();
        unsigned d = atomicAdd(&g_done[idx], 1u);
        if (d == GRID - 1) {           // last to leave: reset for next replay
            g_bar[idx] = 0u;
            __threadfence();
            g_done[idx] = 0u;
        }
    }
    __syncthreads();
}

__device__ __forceinline__ float wcat_elem(const float* __restrict__ basis,
                                           const float* __restrict__ comp,
                                           const float* __restrict__ root,
                                           int IN, int OUT, int i) {
    int J = 3 * OUT;
    int k = i / J;
    int j = i - k * J;
    if (j < 2 * OUT) {
        int r = j / OUT;
        int o = j - r * OUT;
        float v = 0.f;
#pragma unroll
        for (int b = 0; b < 4; b++)
            v += comp[r * 4 + b] * basis[(b * IN + k) * OUT + o];
        return v;
    }
    return root[k * OUT + (j - 2 * OUT)];
}

// fused RGCN agg(64) + next-layer HR for one node (warp-collective)
template <int J2, int NCOL2>
__device__ __forceinline__ void agg64_node(int n, int lane,
                                           const float* __restrict__ HRin,
                                           float* __restrict__ HRout,
                                           const float* __restrict__ rbias,
                                           const float* __restrict__ W) {
    int beg = g_rowptr[n], end = g_rowptr[n + 1];
    float a0[2] = {0.f, 0.f}, a1[2] = {0.f, 0.f};
    int c0 = 0, c1 = 0;
    for (int e = beg; e < end; e++) {
        int s = g_ssrc[e];
        int t = g_stype[e];
        const float* hrow = HRin + s * 192 + t * 64;
        if (t == 0) {
            c0++; a0[0] += hrow[lane]; a0[1] += hrow[lane + 32];
        } else {
            c1++; a1[0] += hrow[lane]; a1[1] += hrow[lane + 32];
        }
    }
    float i0 = 1.f / fmaxf((float)c0, 1.f);
    float i1 = 1.f / fmaxf((float)c1, 1.f);
    float xlo = tanh_ap(HRin[n * 192 + 128 + lane]      + rbias[lane]      + a0[0] * i0 + a1[0] * i1);
    float xhi = tanh_ap(HRin[n * 192 + 128 + lane + 32] + rbias[lane + 32] + a0[1] * i0 + a1[1] * i1);
    float acc[NCOL2];
#pragma unroll
    for (int j = 0; j < NCOL2; j++) acc[j] = 0.f;
#pragma unroll 4
    for (int k = 0; k < 64; k++) {
        float xk = (k < 32) ? __shfl_sync(0xffffffffu, xlo, k)
                            : __shfl_sync(0xffffffffu, xhi, k - 32);
        const float* wr = W + k * J2;
#pragma unroll
        for (int j = 0; j < NCOL2; j++) acc[j] += xk * wr[lane + j * 32];
    }
#pragma unroll
    for (int j = 0; j < NCOL2; j++) HRout[n * J2 + lane + j * 32] = acc[j];
}

// ---------------------------------------------------------------------------
// THE persistent kernel: every phase of the pipeline, barrier-separated.
// ---------------------------------------------------------------------------
__global__ __launch_bounds__(TPB, 2) void k_mega(
    const int* __restrict__ src, const int* __restrict__ dst,
    const int* __restrict__ etype,
    const float* __restrict__ basis0, const float* __restrict__ comp0,
    const float* __restrict__ root0,  const float* __restrict__ rbias0,
    const float* __restrict__ basis1, const float* __restrict__ comp1,
    const float* __restrict__ root1,  const float* __restrict__ rbias1,
    const float* __restrict__ basis2, const float* __restrict__ comp2,
    const float* __restrict__ root2,  const float* __restrict__ rbias2,
    const float* __restrict__ basis3, const float* __restrict__ comp3,
    const float* __restrict__ root3,  const float* __restrict__ rbias3,
    const float* __restrict__ gw,     const float* __restrict__ as,
    const float* __restrict__ ad,     const float* __restrict__ gbias,
    const float* __restrict__ w1,     const float* __restrict__ b1,
    const float* __restrict__ w2,     const float* __restrict__ b2,
    float* __restrict__ out)
{
    __shared__ __align__(16) float smf[6144];   // 24KB union for all phases
    const int tid  = threadIdx.x;
    const int bid  = blockIdx.x;
    const int lane = tid & 31;
    const int gwarp = bid * 8 + (tid >> 5);

    // ---------------- P0: prep (W0, Wcat1..3) + dst histogram ----------------
    {
        const int PREP = 2 * NN * 32 + 6144 + 12288 + 6144 + EE;
        for (int i = bid * TPB + tid; i < PREP; i += GRID * TPB) {
            if (i < 2 * NN * 32) {
                int r   = i / (NN * 32);
                int rem = i - r * (NN * 32);
                int n   = rem >> 5;
                int o   = rem & 31;
                float v = 0.f;
#pragma unroll
                for (int b = 0; b < 4; b++)
                    v += comp0[r * 4 + b] * basis0[(b * NN + n) * 32 + o];
                g_W0[i] = v;
                continue;
            }
            int j = i - 2 * NN * 32;
            if (j < 6144) { g_WcAll[WC1_OFF + j] = wcat_elem(basis1, comp1, root1, 32, 64, j); continue; }
            j -= 6144;
            if (j < 12288) { g_WcAll[WC2_OFF + j] = wcat_elem(basis2, comp2, root2, 64, 64, j); continue; }
            j -= 12288;
            if (j < 6144) { g_WcAll[WC3_OFF + j] = wcat_elem(basis3, comp3, root3, 64, 32, j); continue; }
            j -= 6144;
            atomicAdd(&g_cnt[dst[j]], 1);
        }
    }
    gbar(0);

    // ---------------- P1: exclusive scan (block 0 only) ----------------
    if (bid == 0) {
        int* sp = (int*)smf;
        const int CH = (NN + 255) / 256;   // 24
        int base = tid * CH;
        int s = 0;
        for (int i = 0; i < CH; i++) {
            int idx = base + i;
            if (idx < NN) s += g_cnt[idx];
        }
        sp[tid] = s;
        __syncthreads();
        for (int off = 1; off < 256; off <<= 1) {
            int v = 0;
            if (tid >= off) v = sp[tid - off];
            __syncthreads();
            sp[tid] += v;
            __syncthreads();
        }
        int run = sp[tid] - s;
        for (int i = 0; i < CH; i++) {
            int idx = base + i;
            if (idx < NN) {
                int c = g_cnt[idx];
                g_rowptr[idx] = run;
                g_cursor[idx] = run;
                g_cnt[idx] = 0;          // reset for next replay
                run += c;
            }
        }
        if (tid == 255) g_rowptr[NN] = sp[255];
    }
    gbar(1);

    // ---------------- P2: scatter into CSR ----------------
    for (int e = bid * TPB + tid; e < EE; e += GRID * TPB) {
        int d = dst[e];
        int p = atomicAdd(&g_cursor[d], 1);
        g_ssrc[p]  = src[e];
        g_sdst[p]  = d;
        g_seid[p]  = e;
        g_stype[p] = etype[e];
    }
    gbar(2);

    // ---------------- P3: layer0 (x=I) + HR1 -> g_HRa ----------------
    for (int n = gwarp; n < NN; n += NWARPS) {
        int beg = g_rowptr[n], end = g_rowptr[n + 1];
        float a0 = 0.f, a1 = 0.f;
        int c0 = 0, c1 = 0;
        for (int e = beg; e < end; e++) {
            int s = g_ssrc[e];
            int t = g_stype[e];
            float v = g_W0[(t * NN + s) * 32 + lane];
            if (t == 0) { a0 += v; c0++; } else { a1 += v; c1++; }
        }
        float x = tanh_ap(root0[n * 32 + lane] + rbias0[lane]
                        + a0 / fmaxf((float)c0, 1.f) + a1 / fmaxf((float)c1, 1.f));
        float acc[6] = {0.f, 0.f, 0.f, 0.f, 0.f, 0.f};
        const float* W = g_WcAll + WC1_OFF;
#pragma unroll 4
        for (int k = 0; k < 32; k++) {
            float xk = __shfl_sync(0xffffffffu, x, k);
            const float* wr = W + k * 192;
#pragma unroll
            for (int j = 0; j < 6; j++) acc[j] += xk * wr[lane + j * 32];
        }
#pragma unroll
        for (int j = 0; j < 6; j++) g_HRa[n * 192 + lane + j * 32] = acc[j];
    }
    gbar(3);

    // ---------------- P4: agg1 + HR2 : g_HRa -> g_HRb ----------------
    for (int n = gwarp; n < NN; n += NWARPS)
        agg64_node<192, 6>(n, lane, g_HRa, g_HRb, rbias1, g_WcAll + WC2_OFF);
    gbar(4);

    // ---------------- P5: agg2 + HR3 : g_HRb -> g_HRa (J=96) ----------------
    for (int n = gwarp; n < NN; n += NWARPS)
        agg64_node<96, 3>(n, lane, g_HRb, g_HRa, rbias2, g_WcAll + WC3_OFF);
    gbar(5);

    // ---------------- P6: agg3 + GAT h-GEMM + attdot (8 nodes / block) ------
    {
        float* sx = smf;            // 256 floats: 8 rows x 32 (x3)
        float* sp = smf + 256;      // 2048: per-thread partials (2 halves x 1024)
        int half = tid >> 7;        // 0/1 — two independent 128-thread halves
        int t128 = tid & 127;
        int w8 = tid >> 5;          // 0..7
        for (int task = bid; task < NN / 8; task += GRID) {
            int n0 = task * 8;
            // agg3 for node n0+w8 (warp-parallel over edges)
            {
                int n = n0 + w8;
                int beg = g_rowptr[n], end = g_rowptr[n + 1];
                float a0 = 0.f, a1 = 0.f;
                int c0 = 0, c1 = 0;
                for (int e = beg; e < end; e++) {
                    int s = g_ssrc[e];
                    int t = g_stype[e];
                    float v = g_HRa[s * 96 + t * 32 + lane];
                    if (t == 0) { a0 += v; c0++; } else { a1 += v; c1++; }
                }
                float o = g_HRa[n * 96 + 64 + lane] + rbias3[lane]
                        + a0 / fmaxf((float)c0, 1.f) + a1 / fmaxf((float)c1, 1.f);
                sx[w8 * 32 + lane] = tanh_ap(o);
            }
            __syncthreads();
            // h = x3 @ gw : each half covers 4 rows x 512 cols
            int c4 = t128 << 2;
            float4 acc[4];
#pragma unroll
            for (int r = 0; r < 4; r++) acc[r] = make_float4(0.f, 0.f, 0.f, 0.f);
#pragma unroll 4
            for (int k = 0; k < 32; k++) {
                float4 wv = *(const float4*)(gw + k * 512 + c4);
#pragma unroll
                for (int r = 0; r < 4; r++) {
                    float xv = sx[(half * 4 + r) * 32 + k];
                    acc[r].x += xv * wv.x; acc[r].y += xv * wv.y;
                    acc[r].z += xv * wv.z; acc[r].w += xv * wv.w;
                }
            }
            float4 av = *(const float4*)(as + c4);
            float4 dv = *(const float4*)(ad + c4);
#pragma unroll
            for (int r = 0; r < 4; r++) {
                *(float4*)(g_h + (n0 + half * 4 + r) * 512 + c4) = acc[r];
                sp[half * 1024 + t128 * 8 + r * 2 + 0] =
                    acc[r].x * av.x + acc[r].y * av.y + acc[r].z * av.z + acc[r].w * av.w;
                sp[half * 1024 + t128 * 8 + r * 2 + 1] =
                    acc[r].x * dv.x + acc[r].y * dv.y + acc[r].z * dv.z + acc[r].w * dv.w;
            }
            __syncthreads();
            // warp w8 reduces asv/adv for node n0+w8
            float s1 = 0.f, s2 = 0.f;
#pragma unroll
            for (int i = 0; i < 4; i++) {
                s1 += sp[(w8 >> 2) * 1024 + (lane + 32 * i) * 8 + (w8 & 3) * 2 + 0];
                s2 += sp[(w8 >> 2) * 1024 + (lane + 32 * i) * 8 + (w8 & 3) * 2 + 1];
            }
#pragma unroll
            for (int off = 16; off; off >>= 1) {
                s1 += __shfl_xor_sync(0xffffffffu, s1, off);
                s2 += __shfl_xor_sync(0xffffffffu, s2, off);
            }
            if (lane == 0) { g_asv[n0 + w8] = s1; g_adv[n0 + w8] = s2; }
            __syncthreads();
        }
    }
    gbar(6);

    // ---------------- P7: GAT softmax + aggregate (node / block) ----------
    {
        float* sal  = smf;          // 2048 cached exp(alpha)
        float* sred = smf + 2048;   // 256 reduction
        const int SM_CAP = 2048;
        for (int n = bid; n < NN; n += GRID) {
            int beg = g_rowptr[n], end = g_rowptr[n + 1];
            int deg = end - beg;
            bool cached = deg <= SM_CAP;
            float advn = g_adv[n];
            float self_ex = __expf(lrelu(g_asv[n] + advn));
            float lsum = (tid == 0) ? self_ex : 0.f;
            for (int i = tid; i < deg; i += TPB) {
                float ex = __expf(lrelu(g_asv[g_ssrc[beg + i]] + advn));
                if (cached) sal[i] = ex;
                lsum += ex;
            }
            sred[tid] = lsum;
            __syncthreads();
            if (tid < 128) sred[tid] += sred[tid + 128];
            __syncthreads();
            if (tid < 64) sred[tid] += sred[tid + 64];
            __syncthreads();
            if (tid < 32) {
                float v = sred[tid] + sred[tid + 32];
#pragma unroll
                for (int off = 16; off; off >>= 1)
                    v += __shfl_xor_sync(0xffffffffu, v, off);
                if (tid == 0) sred[0] = v;
            }
            __syncthreads();
            float inv = 1.f / fmaxf(sred[0], 1e-16f);
            // aggregate: thread owns 2 of 512 cols
            float2 hv = ((const float2*)(g_h + n * 512))[tid];
            float sc = self_ex * inv;
            float2 acc = make_float2(sc * hv.x, sc * hv.y);
            for (int e = 0; e < deg; e++) {
                float ex = cached ? sal[e]
                                  : __expf(lrelu(g_asv[g_ssrc[beg + e]] + advn));
                float c = ex * inv;
                int s = g_ssrc[beg + e];
                float2 v = ((const float2*)(g_h + s * 512))[tid];
                acc.x += c * v.x; acc.y += c * v.y;
            }
            float2 b = ((const float2*)gbias)[tid];
            float2 o;
            o.x = fmaxf(acc.x + b.x, 0.f);
            o.y = fmaxf(acc.y + b.y, 0.f);
            ((float2*)(g_xb + n * 512))[tid] = o;
            __syncthreads();
        }
    }
    gbar(7);

    // ---------------- P8: A/B GEMM (188 tile tasks) ----------------
    {
        float (*xs)[64]  = (float(*)[64])smf;          // 2048 floats
        float (*ws)[128] = (float(*)[128])(smf + 2048); // 4096 floats
        for (int t = bid; t < 188; t += GRID) {
            int halfsel = t / 94;
            int m0 = (t - halfsel * 94) * 64;
            const float* wb = w1 + halfsel * (512 * 128);
            int col = (tid & 31) * 4;
            int row = (tid >> 5) * 8;
            ull accp[4][4];
#pragma unroll
            for (int i = 0; i < 4; i++)
#pragma unroll
                for (int j = 0; j < 4; j++) accp[i][j] = pk2(0.f, 0.f);
            for (int k0 = 0; k0 < 512; k0 += 32) {
#pragma unroll
                for (int i = 0; i < 2; i++) {
                    int idx = tid + i * 256;
                    int m = idx >> 3;
                    int k4 = (idx & 7) * 4;
                    float4 v = *(const float4*)(g_xb + (m0 + m) * 512 + k0 + k4);
                    xs[k4 + 0][m] = v.x; xs[k4 + 1][m] = v.y;
                    xs[k4 + 2][m] = v.z; xs[k4 + 3][m] = v.w;
                }
#pragma unroll
                for (int i = 0; i < 4; i++) {
                    int idx = tid + i * 256;
                    int kk = idx >> 5;
                    int c4 = (idx & 31) * 4;
                    *(float4*)&ws[kk][c4] = *(const float4*)(wb + (k0 + kk) * 128 + c4);
                }
                __syncthreads();
#pragma unroll
                for (int kk = 0; kk < 32; kk++) {
                    float4 w = *(const float4*)&ws[kk][col];
                    ull wd0 = pk2(w.x, w.x), wd1 = pk2(w.y, w.y);
                    ull wd2 = pk2(w.z, w.z), wd3 = pk2(w.w, w.w);
#pragma unroll
                    for (int r2 = 0; r2 < 4; r2++) {
                        ull xp = *(const ull*)&xs[kk][row + 2 * r2];
                        fma2(accp[r2][0], xp, wd0);
                        fma2(accp[r2][1], xp, wd1);
                        fma2(accp[r2][2], xp, wd2);
                        fma2(accp[r2][3], xp, wd3);
                    }
                }
                __syncthreads();
            }
            float* ob = halfsel ? g_B : g_A;
#pragma unroll
            for (int r2 = 0; r2 < 4; r2++) {
                float4 vlo, vhi;
                upk2(vlo.x, vhi.x, accp[r2][0]);
                upk2(vlo.y, vhi.y, accp[r2][1]);
                upk2(vlo.z, vhi.z, accp[r2][2]);
                upk2(vlo.w, vhi.w, accp[r2][3]);
                *(float4*)(ob + (m0 + row + 2 * r2 + 0) * 128 + col) = vlo;
                *(float4*)(ob + (m0 + row + 2 * r2 + 1) * 128 + col) = vhi;
            }
        }
    }
    gbar(8);

    // ---------------- P9: edge MLP (CSR order, warp / slot) ----------------
    for (int p = gwarp; p < EE; p += NWARPS) {
        int s = g_ssrc[p], d = g_sdst[p], e = g_seid[p];
        float4 a  = ((const float4*)(g_A + s * 128))[lane];
        float4 b  = ((const float4*)(g_B + d * 128))[lane];
        float4 bb = ((const float4*)b1)[lane];
        float4 w  = ((const float4*)w2)[lane];
        float hx = fmaxf(a.x + b.x + bb.x, 0.f);
        float hy = fmaxf(a.y + b.y + bb.y, 0.f);
        float hz = fmaxf(a.z + b.z + bb.z, 0.f);
        float hw = fmaxf(a.w + b.w + bb.w, 0.f);
        float z = hx * w.x + hy * w.y + hz * w.z + hw * w.w;
#pragma unroll
        for (int off = 16; off; off >>= 1)
            z += __shfl_xor_sync(0xffffffffu, z, off);
        if (lane == 0) {
            z += __ldg(b2);
            out[e] = 1.f / (1.f + __expf(-z));
        }
    }
}

// ---------------------------------------------------------------------------
// Launch — robust input binding by element count (edge_index: 2*EE ints,
// edge_type: EE ints; remaining 24 float inputs keep relative order).
// All kernel arguments derive from d_in/d_out only — never device symbols.
// ---------------------------------------------------------------------------
extern "C" void kernel_launch(void* const* d_in, const int* in_sizes, int n_in,
                              void* d_out, int out_size) {
    int ei_idx = -1, et_idx = -1;
    for (int i = 0; i < n_in; i++) {
        if (in_sizes[i] == 2 * EE) ei_idx = i;
        else if (in_sizes[i] == EE) et_idx = i;
    }
    const float* rest[24];
    int k = 0;
    for (int i = 0; i < n_in && k < 24; i++) {
        if (i == ei_idx || i == et_idx) continue;
        rest[k++] = (const float*)d_in[i];
    }

    const int* edge_index = (const int*)d_in[ei_idx];
    const int* src = edge_index;
    const int* dst = edge_index + EE;
    const int* etype = (const int*)d_in[et_idx];
    float* out = (float*)d_out;

    k_mega<<<GRID, TPB>>>(
        src, dst, etype,
        rest[0],  rest[1],  rest[2],  rest[3],    // basis0 comp0 root0 rbias0
        rest[4],  rest[5],  rest[6],  rest[7],    // layer 1
        rest[8],  rest[9],  rest[10], rest[11],   // layer 2
        rest[12], rest[13], rest[14], rest[15],   // layer 3
        rest[16], rest[17], rest[18], rest[19],   // gat_w att_src att_dst gat_bias
        rest[20], rest[21], rest[22], rest[23],   // w1 b1 w2 b2
        out);
}